// round 12
// baseline (speedup 1.0000x reference)
#include <cuda_runtime.h>
#include <cuda_fp16.h>
#include <math.h>
#include <stdint.h>

// ---------------- problem constants (l = 2, 76x76 head) ----------------
#define IN_H   76
#define IN_W   76
#define PLANE  (IN_H * IN_W)        // 5776 (divisible by 4)
#define BS     32
#define NT     20
#define NA     3
#define NC     80
#define CELLS  (NA * PLANE)         // 17328 per batch item
#define VCELLS4 (CELLS / 4)         // 4332 float4 groups per batch item
#define NVB    ((VCELLS4 + 255) / 256)  // 17 dense x-blocks
#define TOTAL_BLOCKS ((NVB + 1) * BS)   // 576

__device__ __constant__ float c_aw9[9] = {1.5f, 2.375f, 5.f, 4.5f, 9.5f, 9.f, 17.75f, 24.f, 57.375f};
__device__ __constant__ float c_ah9[9] = {2.f, 4.5f, 3.5f, 9.375f, 6.875f, 18.25f, 13.75f, 30.375f, 50.125f};
__device__ __constant__ float c_awl[3] = {1.5f, 2.375f, 5.f};
__device__ __constant__ float c_ahl[3] = {2.f, 4.5f, 3.5f};

#define BOX_RATIO 0.05
#define CLS_RATIO 1.0
#define BALANCE_L 4.0
#define OBJ_RATIO (5.0 * 608.0 * 608.0 / (416.0 * 416.0))

// ---------------- device scratch (zero-initialized at load; self-reset per call) ----------------
__device__ double g_conf_num = 0.0;
__device__ double g_mask_sum = 0.0;
__device__ double g_loc_sum  = 0.0;
__device__ double g_cls_sum  = 0.0;
__device__ int    g_nobj     = 0;
__device__ int    g_done     = 0;

__device__ __forceinline__ float sigfast(float x) { return __fdividef(1.f, 1.f + __expf(-x)); }
// softplus(x) = bce(sigmoid(x), 0);  bce(sigmoid(x), 1) = softplus(-x)
__device__ __forceinline__ float splus(float x) { return __logf(1.f + __expf(x)); }

struct SMatch { int a, gi, gj, cls; float gx, gy, gw, gh; };
struct __align__(16) TBox { __half2 mnx, mxx, mny, mxy; };   // duplicated target bounds

// ---------------- single fused kernel ----------------
// grid (NVB+1, BS): x < NVB -> dense conf pass (4 cells/thread, fp16x2 ignore test),
//                   x == NVB -> match + correction (identical fp16 predicate).
// launch_bounds(256,4): 4 blocks/SM -> 592 slots >= 576 blocks = single wave.
__global__ void __launch_bounds__(256, 4) k_fused(const float* __restrict__ input,
                                                  const float* __restrict__ targets,
                                                  float* __restrict__ out) {
    const int b = blockIdx.y;
    const int tid = threadIdx.x;
    const int wid = tid >> 5, lane = tid & 31;

    if (blockIdx.x == NVB) {
        // ======== match + correction block for batch item b ========
        __shared__ float sminx[NT], smaxx[NT], sminy[NT], smaxy[NT], sarea[NT];
        __shared__ int s_flat[NT];
        __shared__ int s_cnt;
        __shared__ SMatch s_m[NT];
        __shared__ double s_conf, s_mask, s_loc, s_cls;
        if (tid == 0) { s_cnt = 0; s_conf = 0.0; s_mask = 0.0; s_loc = 0.0; s_cls = 0.0; }
        __syncthreads();

        int flat = -1, bn = 0, gi = 0, gj = 0;
        float x = 0.f, y = 0.f, w = 0.f, h = 0.f;
        if (tid < NT) {
            const float* tp = targets + (b * NT + tid) * 5;
            x = tp[0] * (float)IN_W;
            y = tp[1] * (float)IN_H;
            w = tp[2] * (float)IN_W;
            h = tp[3] * (float)IN_H;
            sminx[tid] = x - w * 0.5f; smaxx[tid] = x + w * 0.5f;
            sminy[tid] = y - h * 0.5f; smaxy[tid] = y + h * 0.5f;
            sarea[tid] = w * h;
            float best = -1.f;
            #pragma unroll
            for (int a = 0; a < 9; a++) {
                float inter = fminf(w, c_aw9[a]) * fminf(h, c_ah9[a]);
                float uni   = w * h + c_aw9[a] * c_ah9[a] - inter;
                float r = inter / uni;
                if (r > best) { best = r; bn = a; }
            }
            if (bn < NA) {   // ANCHORS_MASK[2] = [0,1,2]
                gi = min(max((int)floorf(x), 0), IN_W - 1);
                gj = min(max((int)floorf(y), 0), IN_H - 1);
                flat = (bn * IN_H + gj) * IN_W + gi;
            }
            s_flat[tid] = flat;
        }
        __syncthreads();
        if (tid < NT && flat >= 0) {
            // last-wins dedupe
            bool fin = true;
            for (int t2 = tid + 1; t2 < NT; t2++)
                if (s_flat[t2] == flat) { fin = false; break; }
            if (fin) {
                int idx = atomicAdd(&s_cnt, 1);
                SMatch m; m.a = bn; m.gi = gi; m.gj = gj;
                m.gx = x; m.gy = y; m.gw = w; m.gh = h;
                m.cls = (int)targets[(b * NT + tid) * 5 + 4];
                s_m[idx] = m;
            }
        }
        __syncthreads();

        const int cnt = s_cnt;
        for (int c = wid; c < cnt; c += 8) {
            SMatch M = s_m[c];
            const float* base = input + ((size_t)b * 255 + (size_t)M.a * 85) * PLANE
                                      + (size_t)M.gj * IN_W + M.gi;

            float v5 = (lane < 5) ? base[(size_t)lane * PLANE] : 0.f;
            float tx = __shfl_sync(0xffffffffu, v5, 0);
            float ty = __shfl_sync(0xffffffffu, v5, 1);
            float tw = __shfl_sync(0xffffffffu, v5, 2);
            float th = __shfl_sync(0xffffffffu, v5, 3);
            float tc = __shfl_sync(0xffffffffu, v5, 4);

            float clssum = 0.f;
            #pragma unroll
            for (int cc = lane; cc < NC; cc += 32) {
                float tv = base[(size_t)(5 + cc) * PLANE];
                clssum += (cc == M.cls) ? splus(-tv) : splus(tv);
            }

            float px = (float)M.gi + sigfast(tx);
            float py = (float)M.gj + sigfast(ty);
            float pw = __expf(tw) * c_awl[M.a];
            float ph = __expf(th) * c_ahl[M.a];
            float b1minx = px - pw * 0.5f, b1maxx = px + pw * 0.5f;
            float b1miny = py - ph * 0.5f, b1maxy = py + ph * 0.5f;
            float pa = pw * ph;

            // ignore-IoU vs 20 gt boxes — half2 sequence IDENTICAL to dense path
            bool hit_t = false;
            if (lane < NT) {
                __half2 tmnx = __floats2half2_rn(sminx[lane], sminx[lane]);
                __half2 tmxx = __floats2half2_rn(smaxx[lane], smaxx[lane]);
                __half2 tmny = __floats2half2_rn(sminy[lane], sminy[lane]);
                __half2 tmxy = __floats2half2_rn(smaxy[lane], smaxy[lane]);
                __half2 nt2  = __floats2half2_rn(-sarea[lane], -sarea[lane]);
                __half2 cmnx = __floats2half2_rn(b1minx, b1minx);
                __half2 cmxx = __floats2half2_rn(b1maxx, b1maxx);
                __half2 cmny = __floats2half2_rn(b1miny, b1miny);
                __half2 cmxy = __floats2half2_rn(b1maxy, b1maxy);
                const __half2 zero2  = __floats2half2_rn(0.f, 0.f);
                const __half2 three2 = __floats2half2_rn(3.f, 3.f);
                __half2 iw2h = __hmax2(__hsub2(__hmin2(tmxx, cmxx), __hmax2(tmnx, cmnx)), zero2);
                __half2 ih2h = __hsub2(__hmin2(tmxy, cmxy), __hmax2(tmny, cmny));
                __half2 diff = __hfma2(__hmul2(iw2h, ih2h), three2, nt2);
                hit_t = __hgt(__low2half(diff), __float2half_rn(pa));
            }
            unsigned hitmask = __ballot_sync(0xffffffffu, hit_t);
            #pragma unroll
            for (int o = 16; o > 0; o >>= 1)
                clssum += __shfl_down_sync(0xffffffffu, clssum, o);

            if (lane == 0) {
                // ---- CIoU (exact reference math, fp32) ----
                float b2minx = M.gx - M.gw * 0.5f, b2maxx = M.gx + M.gw * 0.5f;
                float b2miny = M.gy - M.gh * 0.5f, b2maxy = M.gy + M.gh * 0.5f;
                float iw = fmaxf(fminf(b1maxx, b2maxx) - fmaxf(b1minx, b2minx), 0.f);
                float ih = fmaxf(fminf(b1maxy, b2maxy) - fmaxf(b1miny, b2miny), 0.f);
                float inter = iw * ih;
                float a2 = M.gw * M.gh;
                float iou = inter / fmaxf(pa + a2 - inter, 1e-6f);
                float cdx = px - M.gx, cdy = py - M.gy;
                float center_d = cdx * cdx + cdy * cdy;
                float ew = fmaxf(fmaxf(b1maxx, b2maxx) - fminf(b1minx, b2minx), 0.f);
                float eh = fmaxf(fmaxf(b1maxy, b2maxy) - fminf(b1miny, b2miny), 0.f);
                float encl = ew * ew + eh * eh;
                float ciou = iou - center_d / fmaxf(encl, 1e-6f);
                const float FOUR_OVER_PI2 = 4.f / (float)(M_PI * M_PI);
                float dat = atanf(pw / fmaxf(ph, 1e-6f)) - atanf(M.gw / fmaxf(M.gh, 1e-6f));
                float v = FOUR_OVER_PI2 * dat * dat;
                float alpha = v / fmaxf(1.f - iou + v, 1e-6f);
                ciou = ciou - alpha * v;

                // ---- conf correction (exact cancel vs dense pass) ----
                float noobj0 = hitmask ? 0.f : 1.f;
                float add = splus(-tc);
                float sub = splus(tc) * noobj0;

                atomicAdd(&s_conf, (double)(add - sub));
                atomicAdd(&s_mask, (double)(1.f - noobj0));
                atomicAdd(&s_loc,  (double)(1.f - ciou));
                atomicAdd(&s_cls,  (double)clssum);
            }
        }
        __syncthreads();
        if (tid == 0) {
            atomicAdd(&g_conf_num, s_conf);
            atomicAdd(&g_mask_sum, s_mask);
            atomicAdd(&g_loc_sum,  s_loc);
            atomicAdd(&g_cls_sum,  s_cls);
            atomicAdd(&g_nobj, cnt);
        }
    } else {
        // ======== dense conf block: 4 cells/thread, two half2 chains ========
        __shared__ TBox    s_tb[NT];
        __shared__ __half2 s_nt2[NT];   // -area duplicated
        if (tid < NT) {
            const float* tp = targets + (b * NT + tid) * 5;
            float gx = tp[0] * (float)IN_W, gy = tp[1] * (float)IN_H;
            float gw = tp[2] * (float)IN_W, gh = tp[3] * (float)IN_H;
            float mnx = gx - gw * 0.5f, mxx = gx + gw * 0.5f;
            float mny = gy - gh * 0.5f, mxy = gy + gh * 0.5f;
            TBox tb;
            tb.mnx = __floats2half2_rn(mnx, mnx);
            tb.mxx = __floats2half2_rn(mxx, mxx);
            tb.mny = __floats2half2_rn(mny, mny);
            tb.mxy = __floats2half2_rn(mxy, mxy);
            s_tb[tid] = tb;
            s_nt2[tid] = __floats2half2_rn(-(gw * gh), -(gw * gh));
        }
        __syncthreads();

        float cnum = 0.f, cmask = 0.f;
        const int v = blockIdx.x * 256 + tid;
        if (v < VCELLS4) {
            const int m0  = v * 4;
            const int a   = m0 / PLANE;
            const int rem = m0 - a * PLANE;
            const int i   = rem / IN_W;
            const int j   = rem - i * IN_W;

            const float* base = input + ((size_t)b * 255 + (size_t)a * 85) * PLANE + rem;
            float4 tx = *(const float4*)(base);
            float4 ty = *(const float4*)(base + PLANE);
            float4 tw = *(const float4*)(base + 2 * PLANE);
            float4 th = *(const float4*)(base + 3 * PLANE);
            float4 tc = *(const float4*)(base + 4 * PLANE);

            float mnx[4], mxx[4], mny[4], mxy[4], pa[4];
            const float tcv[4] = {tc.x, tc.y, tc.z, tc.w};
            {
                const float txa[4] = {tx.x, tx.y, tx.z, tx.w};
                const float tya[4] = {ty.x, ty.y, ty.z, ty.w};
                const float twa[4] = {tw.x, tw.y, tw.z, tw.w};
                const float tha[4] = {th.x, th.y, th.z, th.w};
                #pragma unroll
                for (int k = 0; k < 4; k++) {
                    float px = (float)(j + k) + sigfast(txa[k]);
                    float py = (float)i       + sigfast(tya[k]);
                    float pw = __expf(twa[k]) * c_awl[a];
                    float ph = __expf(tha[k]) * c_ahl[a];
                    mnx[k] = px - pw * 0.5f; mxx[k] = px + pw * 0.5f;
                    mny[k] = py - ph * 0.5f; mxy[k] = py + ph * 0.5f;
                    pa[k] = pw * ph;
                }
            }
            // pack: pair 0 = cells {0,1}, pair 1 = cells {2,3}
            __half2 cmnx[2], cmxx[2], cmny[2], cmxy[2], maxd[2];
            #pragma unroll
            for (int p = 0; p < 2; p++) {
                cmnx[p] = __floats2half2_rn(mnx[2*p], mnx[2*p+1]);
                cmxx[p] = __floats2half2_rn(mxx[2*p], mxx[2*p+1]);
                cmny[p] = __floats2half2_rn(mny[2*p], mny[2*p+1]);
                cmxy[p] = __floats2half2_rn(mxy[2*p], mxy[2*p+1]);
                maxd[p] = __floats2half2_rn(-60000.f, -60000.f);
            }
            const __half2 zero2  = __floats2half2_rn(0.f, 0.f);
            const __half2 three2 = __floats2half2_rn(3.f, 3.f);

            #pragma unroll
            for (int t = 0; t < NT; t++) {
                TBox tb = s_tb[t];                      // LDS.128
                __half2 nt2 = s_nt2[t];                 // LDS.32
                #pragma unroll
                for (int p = 0; p < 2; p++) {
                    __half2 iw2h = __hmax2(__hsub2(__hmin2(tb.mxx, cmxx[p]),
                                                   __hmax2(tb.mnx, cmnx[p])), zero2);
                    __half2 ih2h = __hsub2(__hmin2(tb.mxy, cmxy[p]),
                                           __hmax2(tb.mny, cmny[p]));
                    __half2 diff = __hfma2(__hmul2(iw2h, ih2h), three2, nt2);
                    maxd[p] = __hmax2(maxd[p], diff);
                }
            }

            const bool hit[4] = {
                __hgt(__low2half(maxd[0]),  __float2half_rn(pa[0])),
                __hgt(__high2half(maxd[0]), __float2half_rn(pa[1])),
                __hgt(__low2half(maxd[1]),  __float2half_rn(pa[2])),
                __hgt(__high2half(maxd[1]), __float2half_rn(pa[3]))
            };
            #pragma unroll
            for (int k = 0; k < 4; k++) {
                if (!hit[k]) { cnum += splus(tcv[k]); cmask += 1.f; }
            }
        }

        #pragma unroll
        for (int o = 16; o > 0; o >>= 1) {
            cnum  += __shfl_down_sync(0xffffffffu, cnum,  o);
            cmask += __shfl_down_sync(0xffffffffu, cmask, o);
        }
        __shared__ float rn[8], rm[8];
        if (lane == 0) { rn[wid] = cnum; rm[wid] = cmask; }
        __syncthreads();
        if (wid == 0) {
            float n = (lane < 8) ? rn[lane] : 0.f;
            float k = (lane < 8) ? rm[lane] : 0.f;
            #pragma unroll
            for (int o = 4; o > 0; o >>= 1) {
                n += __shfl_down_sync(0xffffffffu, n, o);
                k += __shfl_down_sync(0xffffffffu, k, o);
            }
            if (lane == 0) {
                atomicAdd(&g_conf_num, (double)n);
                atomicAdd(&g_mask_sum, (double)k);
            }
        }
        __syncthreads();
    }

    // ======== grid-wide completion: last block assembles the loss ========
    if (tid == 0) {
        __threadfence();
        int d = atomicAdd(&g_done, 1);
        if (d == TOTAL_BLOCKS - 1) {
            double nobj = (g_nobj > 0) ? (double)g_nobj : 1.0;
            double loss = g_loc_sum / nobj * BOX_RATIO
                        + g_cls_sum / (nobj * (double)NC) * CLS_RATIO
                        + g_conf_num / fmax(g_mask_sum, 1.0) * BALANCE_L * OBJ_RATIO;
            out[0] = (float)loss;
            // self-reset for the next graph replay
            g_conf_num = 0.0; g_mask_sum = 0.0; g_loc_sum = 0.0; g_cls_sum = 0.0;
            g_nobj = 0; g_done = 0;
        }
    }
}

// ---------------- launcher ----------------
extern "C" void kernel_launch(void* const* d_in, const int* in_sizes, int n_in,
                              void* d_out, int out_size) {
    const float* input   = (const float*)d_in[0];
    const float* targets = (const float*)d_in[1];
    float* out = (float*)d_out;
    (void)in_sizes; (void)n_in; (void)out_size;

    dim3 grid(NVB + 1, BS);
    k_fused<<<grid, 256>>>(input, targets, out);
}

// round 13
// speedup vs baseline: 1.0042x; 1.0042x over previous
#include <cuda_runtime.h>
#include <cuda_fp16.h>
#include <math.h>
#include <stdint.h>

// ---------------- problem constants (l = 2, 76x76 head) ----------------
#define IN_H   76
#define IN_W   76
#define PLANE  (IN_H * IN_W)        // 5776 (divisible by 4)
#define BS     32
#define NT     20
#define NA     3
#define NC     80
#define CELLS  (NA * PLANE)         // 17328 per batch item
#define VCELLS4 (CELLS / 4)         // 4332 float4 groups per batch item
#define TPB    128
#define NVB    ((VCELLS4 + TPB - 1) / TPB)  // 34 dense x-blocks
#define TOTAL_BLOCKS ((NVB + 1) * BS)       // 1120

__device__ __constant__ float c_aw9[9] = {1.5f, 2.375f, 5.f, 4.5f, 9.5f, 9.f, 17.75f, 24.f, 57.375f};
__device__ __constant__ float c_ah9[9] = {2.f, 4.5f, 3.5f, 9.375f, 6.875f, 18.25f, 13.75f, 30.375f, 50.125f};
__device__ __constant__ float c_awl[3] = {1.5f, 2.375f, 5.f};
__device__ __constant__ float c_ahl[3] = {2.f, 4.5f, 3.5f};

#define BOX_RATIO 0.05
#define CLS_RATIO 1.0
#define BALANCE_L 4.0
#define OBJ_RATIO (5.0 * 608.0 * 608.0 / (416.0 * 416.0))

// ---------------- device scratch (zero-initialized at load; self-reset per call) ----------------
__device__ double g_conf_num = 0.0;
__device__ double g_mask_sum = 0.0;
__device__ double g_loc_sum  = 0.0;
__device__ double g_cls_sum  = 0.0;
__device__ int    g_nobj     = 0;
__device__ int    g_done     = 0;

__device__ __forceinline__ float sigfast(float x) { return __fdividef(1.f, 1.f + __expf(-x)); }
// softplus(x) = bce(sigmoid(x), 0);  bce(sigmoid(x), 1) = softplus(-x)
__device__ __forceinline__ float splus(float x) { return __logf(1.f + __expf(x)); }

struct SMatch { int a, gi, gj, cls; float gx, gy, gw, gh; };
struct __align__(16) TBox { __half2 mnx, mxx, mny, mxy; };   // duplicated target bounds

// ---------------- single fused kernel ----------------
// grid (NVB+1, BS): x < NVB -> dense conf pass (4 cells/thread, fp16x2 ignore test),
//                   x == NVB -> match + correction (identical fp16 predicate).
// 128-thread blocks, launch_bounds(128,10): 10 blocks/SM -> 40 warps/SM,
// 1480 block slots >= 1120 blocks = single wave with ~2x the resident warps of R12.
__global__ void __launch_bounds__(TPB, 10) k_fused(const float* __restrict__ input,
                                                   const float* __restrict__ targets,
                                                   float* __restrict__ out) {
    const int b = blockIdx.y;
    const int tid = threadIdx.x;
    const int wid = tid >> 5, lane = tid & 31;

    if (blockIdx.x == NVB) {
        // ======== match + correction block for batch item b (4 warps) ========
        __shared__ float sminx[NT], smaxx[NT], sminy[NT], smaxy[NT], sarea[NT];
        __shared__ int s_flat[NT];
        __shared__ int s_cnt;
        __shared__ SMatch s_m[NT];
        __shared__ double s_conf, s_mask, s_loc, s_cls;
        if (tid == 0) { s_cnt = 0; s_conf = 0.0; s_mask = 0.0; s_loc = 0.0; s_cls = 0.0; }
        __syncthreads();

        int flat = -1, bn = 0, gi = 0, gj = 0;
        float x = 0.f, y = 0.f, w = 0.f, h = 0.f;
        if (tid < NT) {
            const float* tp = targets + (b * NT + tid) * 5;
            x = tp[0] * (float)IN_W;
            y = tp[1] * (float)IN_H;
            w = tp[2] * (float)IN_W;
            h = tp[3] * (float)IN_H;
            sminx[tid] = x - w * 0.5f; smaxx[tid] = x + w * 0.5f;
            sminy[tid] = y - h * 0.5f; smaxy[tid] = y + h * 0.5f;
            sarea[tid] = w * h;
            float best = -1.f;
            #pragma unroll
            for (int a = 0; a < 9; a++) {
                float inter = fminf(w, c_aw9[a]) * fminf(h, c_ah9[a]);
                float uni   = w * h + c_aw9[a] * c_ah9[a] - inter;
                float r = inter / uni;
                if (r > best) { best = r; bn = a; }
            }
            if (bn < NA) {   // ANCHORS_MASK[2] = [0,1,2]
                gi = min(max((int)floorf(x), 0), IN_W - 1);
                gj = min(max((int)floorf(y), 0), IN_H - 1);
                flat = (bn * IN_H + gj) * IN_W + gi;
            }
            s_flat[tid] = flat;
        }
        __syncthreads();
        if (tid < NT && flat >= 0) {
            // last-wins dedupe
            bool fin = true;
            for (int t2 = tid + 1; t2 < NT; t2++)
                if (s_flat[t2] == flat) { fin = false; break; }
            if (fin) {
                int idx = atomicAdd(&s_cnt, 1);
                SMatch m; m.a = bn; m.gi = gi; m.gj = gj;
                m.gx = x; m.gy = y; m.gw = w; m.gh = h;
                m.cls = (int)targets[(b * NT + tid) * 5 + 4];
                s_m[idx] = m;
            }
        }
        __syncthreads();

        const int cnt = s_cnt;
        for (int c = wid; c < cnt; c += 4) {
            SMatch M = s_m[c];
            const float* base = input + ((size_t)b * 255 + (size_t)M.a * 85) * PLANE
                                      + (size_t)M.gj * IN_W + M.gi;

            float v5 = (lane < 5) ? base[(size_t)lane * PLANE] : 0.f;
            float tx = __shfl_sync(0xffffffffu, v5, 0);
            float ty = __shfl_sync(0xffffffffu, v5, 1);
            float tw = __shfl_sync(0xffffffffu, v5, 2);
            float th = __shfl_sync(0xffffffffu, v5, 3);
            float tc = __shfl_sync(0xffffffffu, v5, 4);

            float clssum = 0.f;
            #pragma unroll
            for (int cc = lane; cc < NC; cc += 32) {
                float tv = base[(size_t)(5 + cc) * PLANE];
                clssum += (cc == M.cls) ? splus(-tv) : splus(tv);
            }

            float px = (float)M.gi + sigfast(tx);
            float py = (float)M.gj + sigfast(ty);
            float pw = __expf(tw) * c_awl[M.a];
            float ph = __expf(th) * c_ahl[M.a];
            float b1minx = px - pw * 0.5f, b1maxx = px + pw * 0.5f;
            float b1miny = py - ph * 0.5f, b1maxy = py + ph * 0.5f;
            float pa = pw * ph;

            // ignore-IoU vs 20 gt boxes — half2 sequence IDENTICAL to dense path
            bool hit_t = false;
            if (lane < NT) {
                __half2 tmnx = __floats2half2_rn(sminx[lane], sminx[lane]);
                __half2 tmxx = __floats2half2_rn(smaxx[lane], smaxx[lane]);
                __half2 tmny = __floats2half2_rn(sminy[lane], sminy[lane]);
                __half2 tmxy = __floats2half2_rn(smaxy[lane], smaxy[lane]);
                __half2 nt2  = __floats2half2_rn(-sarea[lane], -sarea[lane]);
                __half2 cmnx = __floats2half2_rn(b1minx, b1minx);
                __half2 cmxx = __floats2half2_rn(b1maxx, b1maxx);
                __half2 cmny = __floats2half2_rn(b1miny, b1miny);
                __half2 cmxy = __floats2half2_rn(b1maxy, b1maxy);
                const __half2 zero2  = __floats2half2_rn(0.f, 0.f);
                const __half2 three2 = __floats2half2_rn(3.f, 3.f);
                __half2 iw2h = __hmax2(__hsub2(__hmin2(tmxx, cmxx), __hmax2(tmnx, cmnx)), zero2);
                __half2 ih2h = __hsub2(__hmin2(tmxy, cmxy), __hmax2(tmny, cmny));
                __half2 diff = __hfma2(__hmul2(iw2h, ih2h), three2, nt2);
                hit_t = __hgt(__low2half(diff), __float2half_rn(pa));
            }
            unsigned hitmask = __ballot_sync(0xffffffffu, hit_t);
            #pragma unroll
            for (int o = 16; o > 0; o >>= 1)
                clssum += __shfl_down_sync(0xffffffffu, clssum, o);

            if (lane == 0) {
                // ---- CIoU (exact reference math, fp32) ----
                float b2minx = M.gx - M.gw * 0.5f, b2maxx = M.gx + M.gw * 0.5f;
                float b2miny = M.gy - M.gh * 0.5f, b2maxy = M.gy + M.gh * 0.5f;
                float iw = fmaxf(fminf(b1maxx, b2maxx) - fmaxf(b1minx, b2minx), 0.f);
                float ih = fmaxf(fminf(b1maxy, b2maxy) - fmaxf(b1miny, b2miny), 0.f);
                float inter = iw * ih;
                float a2 = M.gw * M.gh;
                float iou = inter / fmaxf(pa + a2 - inter, 1e-6f);
                float cdx = px - M.gx, cdy = py - M.gy;
                float center_d = cdx * cdx + cdy * cdy;
                float ew = fmaxf(fmaxf(b1maxx, b2maxx) - fminf(b1minx, b2minx), 0.f);
                float eh = fmaxf(fmaxf(b1maxy, b2maxy) - fminf(b1miny, b2miny), 0.f);
                float encl = ew * ew + eh * eh;
                float ciou = iou - center_d / fmaxf(encl, 1e-6f);
                const float FOUR_OVER_PI2 = 4.f / (float)(M_PI * M_PI);
                float dat = atanf(pw / fmaxf(ph, 1e-6f)) - atanf(M.gw / fmaxf(M.gh, 1e-6f));
                float v = FOUR_OVER_PI2 * dat * dat;
                float alpha = v / fmaxf(1.f - iou + v, 1e-6f);
                ciou = ciou - alpha * v;

                // ---- conf correction (exact cancel vs dense pass) ----
                float noobj0 = hitmask ? 0.f : 1.f;
                float add = splus(-tc);
                float sub = splus(tc) * noobj0;

                atomicAdd(&s_conf, (double)(add - sub));
                atomicAdd(&s_mask, (double)(1.f - noobj0));
                atomicAdd(&s_loc,  (double)(1.f - ciou));
                atomicAdd(&s_cls,  (double)clssum);
            }
        }
        __syncthreads();
        if (tid == 0) {
            atomicAdd(&g_conf_num, s_conf);
            atomicAdd(&g_mask_sum, s_mask);
            atomicAdd(&g_loc_sum,  s_loc);
            atomicAdd(&g_cls_sum,  s_cls);
            atomicAdd(&g_nobj, cnt);
        }
    } else {
        // ======== dense conf block: 4 cells/thread, two half2 chains ========
        __shared__ TBox    s_tb[NT];
        __shared__ __half2 s_nt2[NT];   // -area duplicated
        if (tid < NT) {
            const float* tp = targets + (b * NT + tid) * 5;
            float gx = tp[0] * (float)IN_W, gy = tp[1] * (float)IN_H;
            float gw = tp[2] * (float)IN_W, gh = tp[3] * (float)IN_H;
            float mnx = gx - gw * 0.5f, mxx = gx + gw * 0.5f;
            float mny = gy - gh * 0.5f, mxy = gy + gh * 0.5f;
            TBox tb;
            tb.mnx = __floats2half2_rn(mnx, mnx);
            tb.mxx = __floats2half2_rn(mxx, mxx);
            tb.mny = __floats2half2_rn(mny, mny);
            tb.mxy = __floats2half2_rn(mxy, mxy);
            s_tb[tid] = tb;
            s_nt2[tid] = __floats2half2_rn(-(gw * gh), -(gw * gh));
        }
        __syncthreads();

        float cnum = 0.f, cmask = 0.f;
        const int v = blockIdx.x * TPB + tid;
        if (v < VCELLS4) {
            const int m0  = v * 4;
            const int a   = m0 / PLANE;
            const int rem = m0 - a * PLANE;
            const int i   = rem / IN_W;
            const int j   = rem - i * IN_W;

            const float* base = input + ((size_t)b * 255 + (size_t)a * 85) * PLANE + rem;
            float4 tx = *(const float4*)(base);
            float4 ty = *(const float4*)(base + PLANE);
            float4 tw = *(const float4*)(base + 2 * PLANE);
            float4 th = *(const float4*)(base + 3 * PLANE);
            float4 tc = *(const float4*)(base + 4 * PLANE);

            float mnx[4], mxx[4], mny[4], mxy[4], pa[4];
            const float tcv[4] = {tc.x, tc.y, tc.z, tc.w};
            {
                const float txa[4] = {tx.x, tx.y, tx.z, tx.w};
                const float tya[4] = {ty.x, ty.y, ty.z, ty.w};
                const float twa[4] = {tw.x, tw.y, tw.z, tw.w};
                const float tha[4] = {th.x, th.y, th.z, th.w};
                #pragma unroll
                for (int k = 0; k < 4; k++) {
                    float px = (float)(j + k) + sigfast(txa[k]);
                    float py = (float)i       + sigfast(tya[k]);
                    float pw = __expf(twa[k]) * c_awl[a];
                    float ph = __expf(tha[k]) * c_ahl[a];
                    mnx[k] = px - pw * 0.5f; mxx[k] = px + pw * 0.5f;
                    mny[k] = py - ph * 0.5f; mxy[k] = py + ph * 0.5f;
                    pa[k] = pw * ph;
                }
            }
            // pack: pair 0 = cells {0,1}, pair 1 = cells {2,3}
            __half2 cmnx[2], cmxx[2], cmny[2], cmxy[2], maxd[2];
            #pragma unroll
            for (int p = 0; p < 2; p++) {
                cmnx[p] = __floats2half2_rn(mnx[2*p], mnx[2*p+1]);
                cmxx[p] = __floats2half2_rn(mxx[2*p], mxx[2*p+1]);
                cmny[p] = __floats2half2_rn(mny[2*p], mny[2*p+1]);
                cmxy[p] = __floats2half2_rn(mxy[2*p], mxy[2*p+1]);
                maxd[p] = __floats2half2_rn(-60000.f, -60000.f);
            }
            const __half2 zero2  = __floats2half2_rn(0.f, 0.f);
            const __half2 three2 = __floats2half2_rn(3.f, 3.f);

            #pragma unroll
            for (int t = 0; t < NT; t++) {
                TBox tb = s_tb[t];                      // LDS.128
                __half2 nt2 = s_nt2[t];                 // LDS.32
                #pragma unroll
                for (int p = 0; p < 2; p++) {
                    __half2 iw2h = __hmax2(__hsub2(__hmin2(tb.mxx, cmxx[p]),
                                                   __hmax2(tb.mnx, cmnx[p])), zero2);
                    __half2 ih2h = __hsub2(__hmin2(tb.mxy, cmxy[p]),
                                           __hmax2(tb.mny, cmny[p]));
                    __half2 diff = __hfma2(__hmul2(iw2h, ih2h), three2, nt2);
                    maxd[p] = __hmax2(maxd[p], diff);
                }
            }

            const bool hit[4] = {
                __hgt(__low2half(maxd[0]),  __float2half_rn(pa[0])),
                __hgt(__high2half(maxd[0]), __float2half_rn(pa[1])),
                __hgt(__low2half(maxd[1]),  __float2half_rn(pa[2])),
                __hgt(__high2half(maxd[1]), __float2half_rn(pa[3]))
            };
            #pragma unroll
            for (int k = 0; k < 4; k++) {
                if (!hit[k]) { cnum += splus(tcv[k]); cmask += 1.f; }
            }
        }

        #pragma unroll
        for (int o = 16; o > 0; o >>= 1) {
            cnum  += __shfl_down_sync(0xffffffffu, cnum,  o);
            cmask += __shfl_down_sync(0xffffffffu, cmask, o);
        }
        __shared__ float rn[4], rm[4];
        if (lane == 0) { rn[wid] = cnum; rm[wid] = cmask; }
        __syncthreads();
        if (wid == 0) {
            float n = (lane < 4) ? rn[lane] : 0.f;
            float k = (lane < 4) ? rm[lane] : 0.f;
            #pragma unroll
            for (int o = 2; o > 0; o >>= 1) {
                n += __shfl_down_sync(0xffffffffu, n, o);
                k += __shfl_down_sync(0xffffffffu, k, o);
            }
            if (lane == 0) {
                atomicAdd(&g_conf_num, (double)n);
                atomicAdd(&g_mask_sum, (double)k);
            }
        }
        __syncthreads();
    }

    // ======== grid-wide completion: last block assembles the loss ========
    if (tid == 0) {
        __threadfence();
        int d = atomicAdd(&g_done, 1);
        if (d == TOTAL_BLOCKS - 1) {
            double nobj = (g_nobj > 0) ? (double)g_nobj : 1.0;
            double loss = g_loc_sum / nobj * BOX_RATIO
                        + g_cls_sum / (nobj * (double)NC) * CLS_RATIO
                        + g_conf_num / fmax(g_mask_sum, 1.0) * BALANCE_L * OBJ_RATIO;
            out[0] = (float)loss;
            // self-reset for the next graph replay
            g_conf_num = 0.0; g_mask_sum = 0.0; g_loc_sum = 0.0; g_cls_sum = 0.0;
            g_nobj = 0; g_done = 0;
        }
    }
}

// ---------------- launcher ----------------
extern "C" void kernel_launch(void* const* d_in, const int* in_sizes, int n_in,
                              void* d_out, int out_size) {
    const float* input   = (const float*)d_in[0];
    const float* targets = (const float*)d_in[1];
    float* out = (float*)d_out;
    (void)in_sizes; (void)n_in; (void)out_size;

    dim3 grid(NVB + 1, BS);
    k_fused<<<grid, TPB>>>(input, targets, out);
}

// round 14
// speedup vs baseline: 1.0535x; 1.0490x over previous
#include <cuda_runtime.h>
#include <cuda_fp16.h>
#include <math.h>
#include <stdint.h>

// ---------------- problem constants (l = 2, 76x76 head) ----------------
#define IN_H   76
#define IN_W   76
#define PLANE  (IN_H * IN_W)        // 5776 (divisible by 4)
#define BS     32
#define NT     20
#define NA     3
#define NC     80
#define CELLS  (NA * PLANE)         // 17328 per batch item
#define VCELLS4 (CELLS / 4)         // 4332 float4 groups per batch item
#define NVB    ((VCELLS4 + 255) / 256)  // 17 dense x-blocks
#define TOTAL_BLOCKS ((NVB + 1) * BS)   // 576

__device__ __constant__ float c_aw9[9] = {1.5f, 2.375f, 5.f, 4.5f, 9.5f, 9.f, 17.75f, 24.f, 57.375f};
__device__ __constant__ float c_ah9[9] = {2.f, 4.5f, 3.5f, 9.375f, 6.875f, 18.25f, 13.75f, 30.375f, 50.125f};
__device__ __constant__ float c_awl[3] = {1.5f, 2.375f, 5.f};
__device__ __constant__ float c_ahl[3] = {2.f, 4.5f, 3.5f};

#define BOX_RATIO 0.05
#define CLS_RATIO 1.0
#define BALANCE_L 4.0
#define OBJ_RATIO (5.0 * 608.0 * 608.0 / (416.0 * 416.0))

// ---------------- device scratch (zero-initialized at load; self-reset per call) ----------------
__device__ double g_conf_num = 0.0;
__device__ double g_mask_sum = 0.0;
__device__ double g_loc_sum  = 0.0;
__device__ double g_cls_sum  = 0.0;
__device__ int    g_nobj     = 0;
__device__ int    g_done     = 0;

__device__ __forceinline__ float sigfast(float x) { return __fdividef(1.f, 1.f + __expf(-x)); }
// softplus(x) = bce(sigmoid(x), 0);  bce(sigmoid(x), 1) = softplus(-x)
__device__ __forceinline__ float splus(float x) { return __logf(1.f + __expf(x)); }

struct SMatch { int a, gi, gj, cls; float gx, gy, gw, gh; };
struct __align__(16) TBox { __half2 mnx, mxx, mny, mxy; };   // duplicated target bounds

// ---------------- single fused kernel ----------------
// grid (NVB+1, BS): x < NVB -> dense conf pass (4 cells/thread, fp16x2 ignore test),
//                   x == NVB -> match + correction (identical fp16 predicate).
// launch_bounds(256,4): 4 blocks/SM -> 592 slots >= 576 blocks = single wave.
__global__ void __launch_bounds__(256, 4) k_fused(const float* __restrict__ input,
                                                  const float* __restrict__ targets,
                                                  float* __restrict__ out) {
    const int b = blockIdx.y;
    const int tid = threadIdx.x;
    const int wid = tid >> 5, lane = tid & 31;

    if (blockIdx.x == NVB) {
        // ======== match + correction block for batch item b ========
        __shared__ float sminx[NT], smaxx[NT], sminy[NT], smaxy[NT], sarea[NT];
        __shared__ int s_flat[NT];
        __shared__ int s_cnt;
        __shared__ SMatch s_m[NT];
        __shared__ double s_conf, s_mask, s_loc, s_cls;
        if (tid == 0) { s_cnt = 0; s_conf = 0.0; s_mask = 0.0; s_loc = 0.0; s_cls = 0.0; }
        __syncthreads();

        int flat = -1, bn = 0, gi = 0, gj = 0;
        float x = 0.f, y = 0.f, w = 0.f, h = 0.f;
        if (tid < NT) {
            const float* tp = targets + (b * NT + tid) * 5;
            x = tp[0] * (float)IN_W;
            y = tp[1] * (float)IN_H;
            w = tp[2] * (float)IN_W;
            h = tp[3] * (float)IN_H;
            sminx[tid] = x - w * 0.5f; smaxx[tid] = x + w * 0.5f;
            sminy[tid] = y - h * 0.5f; smaxy[tid] = y + h * 0.5f;
            sarea[tid] = w * h;
            float best = -1.f;
            #pragma unroll
            for (int a = 0; a < 9; a++) {
                float inter = fminf(w, c_aw9[a]) * fminf(h, c_ah9[a]);
                float uni   = w * h + c_aw9[a] * c_ah9[a] - inter;
                float r = inter / uni;
                if (r > best) { best = r; bn = a; }
            }
            if (bn < NA) {   // ANCHORS_MASK[2] = [0,1,2]
                gi = min(max((int)floorf(x), 0), IN_W - 1);
                gj = min(max((int)floorf(y), 0), IN_H - 1);
                flat = (bn * IN_H + gj) * IN_W + gi;
            }
            s_flat[tid] = flat;
        }
        __syncthreads();
        if (tid < NT && flat >= 0) {
            // last-wins dedupe
            bool fin = true;
            for (int t2 = tid + 1; t2 < NT; t2++)
                if (s_flat[t2] == flat) { fin = false; break; }
            if (fin) {
                int idx = atomicAdd(&s_cnt, 1);
                SMatch m; m.a = bn; m.gi = gi; m.gj = gj;
                m.gx = x; m.gy = y; m.gw = w; m.gh = h;
                m.cls = (int)targets[(b * NT + tid) * 5 + 4];
                s_m[idx] = m;
            }
        }
        __syncthreads();

        const int cnt = s_cnt;
        for (int c = wid; c < cnt; c += 8) {
            SMatch M = s_m[c];
            const float* base = input + ((size_t)b * 255 + (size_t)M.a * 85) * PLANE
                                      + (size_t)M.gj * IN_W + M.gi;

            float v5 = (lane < 5) ? base[(size_t)lane * PLANE] : 0.f;
            float tx = __shfl_sync(0xffffffffu, v5, 0);
            float ty = __shfl_sync(0xffffffffu, v5, 1);
            float tw = __shfl_sync(0xffffffffu, v5, 2);
            float th = __shfl_sync(0xffffffffu, v5, 3);
            float tc = __shfl_sync(0xffffffffu, v5, 4);

            float clssum = 0.f;
            #pragma unroll
            for (int cc = lane; cc < NC; cc += 32) {
                float tv = base[(size_t)(5 + cc) * PLANE];
                clssum += (cc == M.cls) ? splus(-tv) : splus(tv);
            }

            float px = (float)M.gi + sigfast(tx);
            float py = (float)M.gj + sigfast(ty);
            float pw = __expf(tw) * c_awl[M.a];
            float ph = __expf(th) * c_ahl[M.a];
            float b1minx = px - pw * 0.5f, b1maxx = px + pw * 0.5f;
            float b1miny = py - ph * 0.5f, b1maxy = py + ph * 0.5f;
            float pa = pw * ph;

            // ignore-IoU vs 20 gt boxes — half2 sequence IDENTICAL to dense path
            bool hit_t = false;
            if (lane < NT) {
                __half2 tmnx = __floats2half2_rn(sminx[lane], sminx[lane]);
                __half2 tmxx = __floats2half2_rn(smaxx[lane], smaxx[lane]);
                __half2 tmny = __floats2half2_rn(sminy[lane], sminy[lane]);
                __half2 tmxy = __floats2half2_rn(smaxy[lane], smaxy[lane]);
                __half2 nt2  = __floats2half2_rn(-sarea[lane], -sarea[lane]);
                __half2 cmnx = __floats2half2_rn(b1minx, b1minx);
                __half2 cmxx = __floats2half2_rn(b1maxx, b1maxx);
                __half2 cmny = __floats2half2_rn(b1miny, b1miny);
                __half2 cmxy = __floats2half2_rn(b1maxy, b1maxy);
                const __half2 zero2  = __floats2half2_rn(0.f, 0.f);
                const __half2 three2 = __floats2half2_rn(3.f, 3.f);
                __half2 iw2h = __hmax2(__hsub2(__hmin2(tmxx, cmxx), __hmax2(tmnx, cmnx)), zero2);
                __half2 ih2h = __hsub2(__hmin2(tmxy, cmxy), __hmax2(tmny, cmny));
                __half2 diff = __hfma2(__hmul2(iw2h, ih2h), three2, nt2);
                hit_t = __hgt(__low2half(diff), __float2half_rn(pa));
            }
            unsigned hitmask = __ballot_sync(0xffffffffu, hit_t);
            #pragma unroll
            for (int o = 16; o > 0; o >>= 1)
                clssum += __shfl_down_sync(0xffffffffu, clssum, o);

            if (lane == 0) {
                // ---- CIoU (exact reference math, fp32) ----
                float b2minx = M.gx - M.gw * 0.5f, b2maxx = M.gx + M.gw * 0.5f;
                float b2miny = M.gy - M.gh * 0.5f, b2maxy = M.gy + M.gh * 0.5f;
                float iw = fmaxf(fminf(b1maxx, b2maxx) - fmaxf(b1minx, b2minx), 0.f);
                float ih = fmaxf(fminf(b1maxy, b2maxy) - fmaxf(b1miny, b2miny), 0.f);
                float inter = iw * ih;
                float a2 = M.gw * M.gh;
                float iou = inter / fmaxf(pa + a2 - inter, 1e-6f);
                float cdx = px - M.gx, cdy = py - M.gy;
                float center_d = cdx * cdx + cdy * cdy;
                float ew = fmaxf(fmaxf(b1maxx, b2maxx) - fminf(b1minx, b2minx), 0.f);
                float eh = fmaxf(fmaxf(b1maxy, b2maxy) - fminf(b1miny, b2miny), 0.f);
                float encl = ew * ew + eh * eh;
                float ciou = iou - center_d / fmaxf(encl, 1e-6f);
                const float FOUR_OVER_PI2 = 4.f / (float)(M_PI * M_PI);
                float dat = atanf(pw / fmaxf(ph, 1e-6f)) - atanf(M.gw / fmaxf(M.gh, 1e-6f));
                float v = FOUR_OVER_PI2 * dat * dat;
                float alpha = v / fmaxf(1.f - iou + v, 1e-6f);
                ciou = ciou - alpha * v;

                // ---- conf correction (exact cancel vs dense pass) ----
                float noobj0 = hitmask ? 0.f : 1.f;
                float add = splus(-tc);
                float sub = splus(tc) * noobj0;

                atomicAdd(&s_conf, (double)(add - sub));
                atomicAdd(&s_mask, (double)(1.f - noobj0));
                atomicAdd(&s_loc,  (double)(1.f - ciou));
                atomicAdd(&s_cls,  (double)clssum);
            }
        }
        __syncthreads();
        if (tid == 0) {
            atomicAdd(&g_conf_num, s_conf);
            atomicAdd(&g_mask_sum, s_mask);
            atomicAdd(&g_loc_sum,  s_loc);
            atomicAdd(&g_cls_sum,  s_cls);
            atomicAdd(&g_nobj, cnt);
        }
    } else {
        // ======== dense conf block: 4 cells/thread, two half2 chains, branch-free epilogue ========
        __shared__ TBox    s_tb[NT];
        __shared__ __half2 s_nt2[NT];   // -area duplicated
        if (tid < NT) {
            const float* tp = targets + (b * NT + tid) * 5;
            float gx = tp[0] * (float)IN_W, gy = tp[1] * (float)IN_H;
            float gw = tp[2] * (float)IN_W, gh = tp[3] * (float)IN_H;
            float mnx = gx - gw * 0.5f, mxx = gx + gw * 0.5f;
            float mny = gy - gh * 0.5f, mxy = gy + gh * 0.5f;
            TBox tb;
            tb.mnx = __floats2half2_rn(mnx, mnx);
            tb.mxx = __floats2half2_rn(mxx, mxx);
            tb.mny = __floats2half2_rn(mny, mny);
            tb.mxy = __floats2half2_rn(mxy, mxy);
            s_tb[tid] = tb;
            s_nt2[tid] = __floats2half2_rn(-(gw * gh), -(gw * gh));
        }
        __syncthreads();

        float cnum = 0.f, cmask = 0.f;
        const int v = blockIdx.x * 256 + tid;
        if (v < VCELLS4) {
            const int m0  = v * 4;
            const int a   = m0 / PLANE;
            const int rem = m0 - a * PLANE;
            const int i   = rem / IN_W;
            const int j   = rem - i * IN_W;

            const float* base = input + ((size_t)b * 255 + (size_t)a * 85) * PLANE + rem;
            float4 tx = *(const float4*)(base);
            float4 ty = *(const float4*)(base + PLANE);
            float4 tw = *(const float4*)(base + 2 * PLANE);
            float4 th = *(const float4*)(base + 3 * PLANE);
            float4 tc = *(const float4*)(base + 4 * PLANE);

            float mnx[4], mxx[4], mny[4], mxy[4], pa[4];
            const float tcv[4] = {tc.x, tc.y, tc.z, tc.w};
            {
                const float txa[4] = {tx.x, tx.y, tx.z, tx.w};
                const float tya[4] = {ty.x, ty.y, ty.z, ty.w};
                const float twa[4] = {tw.x, tw.y, tw.z, tw.w};
                const float tha[4] = {th.x, th.y, th.z, th.w};
                #pragma unroll
                for (int k = 0; k < 4; k++) {
                    float px = (float)(j + k) + sigfast(txa[k]);
                    float py = (float)i       + sigfast(tya[k]);
                    float pw = __expf(twa[k]) * c_awl[a];
                    float ph = __expf(tha[k]) * c_ahl[a];
                    mnx[k] = px - pw * 0.5f; mxx[k] = px + pw * 0.5f;
                    mny[k] = py - ph * 0.5f; mxy[k] = py + ph * 0.5f;
                    pa[k] = pw * ph;
                }
            }
            // pack: pair 0 = cells {0,1}, pair 1 = cells {2,3}
            __half2 cmnx[2], cmxx[2], cmny[2], cmxy[2], maxd[2];
            #pragma unroll
            for (int p = 0; p < 2; p++) {
                cmnx[p] = __floats2half2_rn(mnx[2*p], mnx[2*p+1]);
                cmxx[p] = __floats2half2_rn(mxx[2*p], mxx[2*p+1]);
                cmny[p] = __floats2half2_rn(mny[2*p], mny[2*p+1]);
                cmxy[p] = __floats2half2_rn(mxy[2*p], mxy[2*p+1]);
                maxd[p] = __floats2half2_rn(-60000.f, -60000.f);
            }
            const __half2 zero2  = __floats2half2_rn(0.f, 0.f);
            const __half2 three2 = __floats2half2_rn(3.f, 3.f);

            #pragma unroll
            for (int t = 0; t < NT; t++) {
                TBox tb = s_tb[t];                      // LDS.128
                __half2 nt2 = s_nt2[t];                 // LDS.32
                #pragma unroll
                for (int p = 0; p < 2; p++) {
                    __half2 iw2h = __hmax2(__hsub2(__hmin2(tb.mxx, cmnx[p] /*dummy reuse? no*/), __hmax2(tb.mnx, cmnx[p])), zero2);
                    // NOTE: corrected below — keep exact formulation
                    iw2h = __hmax2(__hsub2(__hmin2(tb.mxx, cmxx[p]),
                                           __hmax2(tb.mnx, cmnx[p])), zero2);
                    __half2 ih2h = __hsub2(__hmin2(tb.mxy, cmxy[p]),
                                           __hmax2(tb.mny, cmny[p]));
                    __half2 diff = __hfma2(__hmul2(iw2h, ih2h), three2, nt2);
                    maxd[p] = __hmax2(maxd[p], diff);
                }
            }

            // branch-free epilogue: mask-multiply accumulation
            const float md[4] = {
                __half2float(__low2half(maxd[0])),
                __half2float(__high2half(maxd[0])),
                __half2float(__low2half(maxd[1])),
                __half2float(__high2half(maxd[1]))
            };
            #pragma unroll
            for (int k = 0; k < 4; k++) {
                // same decision as __hgt(maxd, __float2half_rn(pa)): compare in fp16 domain
                float m = (md[k] > __half2float(__float2half_rn(pa[k]))) ? 0.f : 1.f;
                cnum  = fmaf(splus(tcv[k]), m, cnum);
                cmask += m;
            }
        }

        #pragma unroll
        for (int o = 16; o > 0; o >>= 1) {
            cnum  += __shfl_down_sync(0xffffffffu, cnum,  o);
            cmask += __shfl_down_sync(0xffffffffu, cmask, o);
        }
        __shared__ float rn[8], rm[8];
        if (lane == 0) { rn[wid] = cnum; rm[wid] = cmask; }
        __syncthreads();
        if (wid == 0) {
            float n = (lane < 8) ? rn[lane] : 0.f;
            float k = (lane < 8) ? rm[lane] : 0.f;
            #pragma unroll
            for (int o = 4; o > 0; o >>= 1) {
                n += __shfl_down_sync(0xffffffffu, n, o);
                k += __shfl_down_sync(0xffffffffu, k, o);
            }
            if (lane == 0) {
                atomicAdd(&g_conf_num, (double)n);
                atomicAdd(&g_mask_sum, (double)k);
            }
        }
        __syncthreads();
    }

    // ======== grid-wide completion: last block assembles the loss ========
    if (tid == 0) {
        __threadfence();
        int d = atomicAdd(&g_done, 1);
        if (d == TOTAL_BLOCKS - 1) {
            double nobj = (g_nobj > 0) ? (double)g_nobj : 1.0;
            double loss = g_loc_sum / nobj * BOX_RATIO
                        + g_cls_sum / (nobj * (double)NC) * CLS_RATIO
                        + g_conf_num / fmax(g_mask_sum, 1.0) * BALANCE_L * OBJ_RATIO;
            out[0] = (float)loss;
            // self-reset for the next graph replay
            g_conf_num = 0.0; g_mask_sum = 0.0; g_loc_sum = 0.0; g_cls_sum = 0.0;
            g_nobj = 0; g_done = 0;
        }
    }
}

// ---------------- launcher ----------------
extern "C" void kernel_launch(void* const* d_in, const int* in_sizes, int n_in,
                              void* d_out, int out_size) {
    const float* input   = (const float*)d_in[0];
    const float* targets = (const float*)d_in[1];
    float* out = (float*)d_out;
    (void)in_sizes; (void)n_in; (void)out_size;

    dim3 grid(NVB + 1, BS);
    k_fused<<<grid, 256>>>(input, targets, out);
}

// round 15
// speedup vs baseline: 1.1855x; 1.1253x over previous
#include <cuda_runtime.h>
#include <cuda_fp16.h>
#include <math.h>
#include <stdint.h>

// ---------------- problem constants (l = 2, 76x76 head) ----------------
#define IN_H   76
#define IN_W   76
#define PLANE  (IN_H * IN_W)        // 5776 (divisible by 4)
#define BS     32
#define NT     20
#define NA     3
#define NC     80
#define CELLS  (NA * PLANE)         // 17328 per batch item
#define VCELLS4 (CELLS / 4)         // 4332 float4 groups per batch item
#define NVB    ((VCELLS4 + 255) / 256)  // 17 dense x-blocks
#define TOTAL_BLOCKS ((NVB + 1) * BS)   // 576

__device__ __constant__ float c_aw9[9] = {1.5f, 2.375f, 5.f, 4.5f, 9.5f, 9.f, 17.75f, 24.f, 57.375f};
__device__ __constant__ float c_ah9[9] = {2.f, 4.5f, 3.5f, 9.375f, 6.875f, 18.25f, 13.75f, 30.375f, 50.125f};
__device__ __constant__ float c_awl[3] = {1.5f, 2.375f, 5.f};
__device__ __constant__ float c_ahl[3] = {2.f, 4.5f, 3.5f};

#define BOX_RATIO 0.05
#define CLS_RATIO 1.0
#define BALANCE_L 4.0
#define OBJ_RATIO (5.0 * 608.0 * 608.0 / (416.0 * 416.0))

// ---------------- device scratch (zero-initialized at load; self-reset per call) ----------------
__device__ double g_conf_num = 0.0;
__device__ double g_mask_sum = 0.0;
__device__ double g_loc_sum  = 0.0;
__device__ double g_cls_sum  = 0.0;
__device__ int    g_nobj     = 0;
__device__ int    g_done     = 0;

__device__ __forceinline__ float sigfast(float x) { return __fdividef(1.f, 1.f + __expf(-x)); }
// softplus(x) = bce(sigmoid(x), 0);  bce(sigmoid(x), 1) = softplus(-x)
__device__ __forceinline__ float splus(float x) { return __logf(1.f + __expf(x)); }

struct SMatch { int a, gi, gj, cls; float gx, gy, gw, gh; };
struct __align__(16) TBox { __half2 mnx, mxx, mny, mxy; };   // duplicated target bounds

// ---------------- single fused kernel ----------------
// grid (NVB+1, BS): x < NVB  -> dense conf pass (4 cells/thread, fp16x2 ignore test,
//                              block-level conservative y-pruning of targets),
//                   x == NVB -> match + correction (identical fp16 predicate, all 20 targets).
// launch_bounds(256,4): 4 blocks/SM -> 592 slots >= 576 blocks = single wave.
__global__ void __launch_bounds__(256, 4) k_fused(const float* __restrict__ input,
                                                  const float* __restrict__ targets,
                                                  float* __restrict__ out) {
    const int b = blockIdx.y;
    const int tid = threadIdx.x;
    const int wid = tid >> 5, lane = tid & 31;

    if (blockIdx.x == NVB) {
        // ======== match + correction block for batch item b ========
        __shared__ float sminx[NT], smaxx[NT], sminy[NT], smaxy[NT], sarea[NT];
        __shared__ int s_flat[NT];
        __shared__ int s_cnt;
        __shared__ SMatch s_m[NT];
        __shared__ double s_conf, s_mask, s_loc, s_cls;
        if (tid == 0) { s_cnt = 0; s_conf = 0.0; s_mask = 0.0; s_loc = 0.0; s_cls = 0.0; }
        __syncthreads();

        int flat = -1, bn = 0, gi = 0, gj = 0;
        float x = 0.f, y = 0.f, w = 0.f, h = 0.f;
        if (tid < NT) {
            const float* tp = targets + (b * NT + tid) * 5;
            x = tp[0] * (float)IN_W;
            y = tp[1] * (float)IN_H;
            w = tp[2] * (float)IN_W;
            h = tp[3] * (float)IN_H;
            sminx[tid] = x - w * 0.5f; smaxx[tid] = x + w * 0.5f;
            sminy[tid] = y - h * 0.5f; smaxy[tid] = y + h * 0.5f;
            sarea[tid] = w * h;
            float best = -1.f;
            #pragma unroll
            for (int a = 0; a < 9; a++) {
                float inter = fminf(w, c_aw9[a]) * fminf(h, c_ah9[a]);
                float uni   = w * h + c_aw9[a] * c_ah9[a] - inter;
                float r = inter / uni;
                if (r > best) { best = r; bn = a; }
            }
            if (bn < NA) {   // ANCHORS_MASK[2] = [0,1,2]
                gi = min(max((int)floorf(x), 0), IN_W - 1);
                gj = min(max((int)floorf(y), 0), IN_H - 1);
                flat = (bn * IN_H + gj) * IN_W + gi;
            }
            s_flat[tid] = flat;
        }
        __syncthreads();
        if (tid < NT && flat >= 0) {
            // last-wins dedupe
            bool fin = true;
            for (int t2 = tid + 1; t2 < NT; t2++)
                if (s_flat[t2] == flat) { fin = false; break; }
            if (fin) {
                int idx = atomicAdd(&s_cnt, 1);
                SMatch m; m.a = bn; m.gi = gi; m.gj = gj;
                m.gx = x; m.gy = y; m.gw = w; m.gh = h;
                m.cls = (int)targets[(b * NT + tid) * 5 + 4];
                s_m[idx] = m;
            }
        }
        __syncthreads();

        const int cnt = s_cnt;
        for (int c = wid; c < cnt; c += 8) {
            SMatch M = s_m[c];
            const float* base = input + ((size_t)b * 255 + (size_t)M.a * 85) * PLANE
                                      + (size_t)M.gj * IN_W + M.gi;

            float v5 = (lane < 5) ? base[(size_t)lane * PLANE] : 0.f;
            float tx = __shfl_sync(0xffffffffu, v5, 0);
            float ty = __shfl_sync(0xffffffffu, v5, 1);
            float tw = __shfl_sync(0xffffffffu, v5, 2);
            float th = __shfl_sync(0xffffffffu, v5, 3);
            float tc = __shfl_sync(0xffffffffu, v5, 4);

            float clssum = 0.f;
            #pragma unroll
            for (int cc = lane; cc < NC; cc += 32) {
                float tv = base[(size_t)(5 + cc) * PLANE];
                clssum += (cc == M.cls) ? splus(-tv) : splus(tv);
            }

            float px = (float)M.gi + sigfast(tx);
            float py = (float)M.gj + sigfast(ty);
            float pw = __expf(tw) * c_awl[M.a];
            float ph = __expf(th) * c_ahl[M.a];
            float b1minx = px - pw * 0.5f, b1maxx = px + pw * 0.5f;
            float b1miny = py - ph * 0.5f, b1maxy = py + ph * 0.5f;
            float pa = pw * ph;

            // ignore-IoU vs 20 gt boxes — half2 sequence IDENTICAL to dense path
            bool hit_t = false;
            if (lane < NT) {
                __half2 tmnx = __floats2half2_rn(sminx[lane], sminx[lane]);
                __half2 tmxx = __floats2half2_rn(smaxx[lane], smaxx[lane]);
                __half2 tmny = __floats2half2_rn(sminy[lane], sminy[lane]);
                __half2 tmxy = __floats2half2_rn(smaxy[lane], smaxy[lane]);
                __half2 nt2  = __floats2half2_rn(-sarea[lane], -sarea[lane]);
                __half2 cmnx = __floats2half2_rn(b1minx, b1minx);
                __half2 cmxx = __floats2half2_rn(b1maxx, b1maxx);
                __half2 cmny = __floats2half2_rn(b1miny, b1miny);
                __half2 cmxy = __floats2half2_rn(b1maxy, b1maxy);
                const __half2 zero2  = __floats2half2_rn(0.f, 0.f);
                const __half2 three2 = __floats2half2_rn(3.f, 3.f);
                __half2 iw2h = __hmax2(__hsub2(__hmin2(tmxx, cmxx), __hmax2(tmnx, cmnx)), zero2);
                __half2 ih2h = __hsub2(__hmin2(tmxy, cmxy), __hmax2(tmny, cmny));
                __half2 diff = __hfma2(__hmul2(iw2h, ih2h), three2, nt2);
                hit_t = __hgt(__low2half(diff), __float2half_rn(pa));
            }
            unsigned hitmask = __ballot_sync(0xffffffffu, hit_t);
            #pragma unroll
            for (int o = 16; o > 0; o >>= 1)
                clssum += __shfl_down_sync(0xffffffffu, clssum, o);

            if (lane == 0) {
                // ---- CIoU (exact reference math, fp32) ----
                float b2minx = M.gx - M.gw * 0.5f, b2maxx = M.gx + M.gw * 0.5f;
                float b2miny = M.gy - M.gh * 0.5f, b2maxy = M.gy + M.gh * 0.5f;
                float iw = fmaxf(fminf(b1maxx, b2maxx) - fmaxf(b1minx, b2minx), 0.f);
                float ih = fmaxf(fminf(b1maxy, b2maxy) - fmaxf(b1miny, b2miny), 0.f);
                float inter = iw * ih;
                float a2 = M.gw * M.gh;
                float iou = inter / fmaxf(pa + a2 - inter, 1e-6f);
                float cdx = px - M.gx, cdy = py - M.gy;
                float center_d = cdx * cdx + cdy * cdy;
                float ew = fmaxf(fmaxf(b1maxx, b2maxx) - fminf(b1minx, b2minx), 0.f);
                float eh = fmaxf(fmaxf(b1maxy, b2maxy) - fminf(b1miny, b2miny), 0.f);
                float encl = ew * ew + eh * eh;
                float ciou = iou - center_d / fmaxf(encl, 1e-6f);
                const float FOUR_OVER_PI2 = 4.f / (float)(M_PI * M_PI);
                float dat = atanf(pw / fmaxf(ph, 1e-6f)) - atanf(M.gw / fmaxf(M.gh, 1e-6f));
                float v = FOUR_OVER_PI2 * dat * dat;
                float alpha = v / fmaxf(1.f - iou + v, 1e-6f);
                ciou = ciou - alpha * v;

                // ---- conf correction (exact cancel vs dense pass) ----
                float noobj0 = hitmask ? 0.f : 1.f;
                float add = splus(-tc);
                float sub = splus(tc) * noobj0;

                atomicAdd(&s_conf, (double)(add - sub));
                atomicAdd(&s_mask, (double)(1.f - noobj0));
                atomicAdd(&s_loc,  (double)(1.f - ciou));
                atomicAdd(&s_cls,  (double)clssum);
            }
        }
        __syncthreads();
        if (tid == 0) {
            atomicAdd(&g_conf_num, s_conf);
            atomicAdd(&g_mask_sum, s_mask);
            atomicAdd(&g_loc_sum,  s_loc);
            atomicAdd(&g_cls_sum,  s_cls);
            atomicAdd(&g_nobj, cnt);
        }
    } else {
        // ======== dense conf block: 4 cells/thread, half2 chains + conservative y-pruning ========
        __shared__ TBox    s_tb[NT];
        __shared__ __half2 s_nt2[NT];       // -area duplicated
        __shared__ float2  s_tyf[NT];       // fp32 {tminy, tmaxy} for pruning
        __shared__ TBox    s_ctb[NT];       // compacted targets
        __shared__ __half2 s_cnt2[NT];
        __shared__ float   s_red_mn[8], s_red_mx[8];
        __shared__ float   s_ymin, s_ymax;
        __shared__ int     s_live;
        if (tid < NT) {
            const float* tp = targets + (b * NT + tid) * 5;
            float gx = tp[0] * (float)IN_W, gy = tp[1] * (float)IN_H;
            float gw = tp[2] * (float)IN_W, gh = tp[3] * (float)IN_H;
            float mnx = gx - gw * 0.5f, mxx = gx + gw * 0.5f;
            float mny = gy - gh * 0.5f, mxy = gy + gh * 0.5f;
            TBox tb;
            tb.mnx = __floats2half2_rn(mnx, mnx);
            tb.mxx = __floats2half2_rn(mxx, mxx);
            tb.mny = __floats2half2_rn(mny, mny);
            tb.mxy = __floats2half2_rn(mxy, mxy);
            s_tb[tid] = tb;
            s_nt2[tid] = __floats2half2_rn(-(gw * gh), -(gw * gh));
            s_tyf[tid] = make_float2(mny, mxy);
        }
        __syncthreads();

        float cnum = 0.f, cmask = 0.f;
        const int v = blockIdx.x * 256 + tid;
        const bool active = (v < VCELLS4);

        float mnx[4], mxx[4], mny[4], mxy[4], pa[4];
        float tcv[4] = {0.f, 0.f, 0.f, 0.f};
        float ly0 = 1e30f, ly1 = -1e30f;
        if (active) {
            const int m0  = v * 4;
            const int a   = m0 / PLANE;
            const int rem = m0 - a * PLANE;
            const int i   = rem / IN_W;
            const int j   = rem - i * IN_W;

            const float* base = input + ((size_t)b * 255 + (size_t)a * 85) * PLANE + rem;
            float4 tx = *(const float4*)(base);
            float4 ty = *(const float4*)(base + PLANE);
            float4 tw = *(const float4*)(base + 2 * PLANE);
            float4 th = *(const float4*)(base + 3 * PLANE);
            float4 tc = *(const float4*)(base + 4 * PLANE);

            const float txa[4] = {tx.x, tx.y, tx.z, tx.w};
            const float tya[4] = {ty.x, ty.y, ty.z, ty.w};
            const float twa[4] = {tw.x, tw.y, tw.z, tw.w};
            const float tha[4] = {th.x, th.y, th.z, th.w};
            tcv[0] = tc.x; tcv[1] = tc.y; tcv[2] = tc.z; tcv[3] = tc.w;
            #pragma unroll
            for (int k = 0; k < 4; k++) {
                float px = (float)(j + k) + sigfast(txa[k]);
                float py = (float)i       + sigfast(tya[k]);
                float pw = __expf(twa[k]) * c_awl[a];
                float ph = __expf(tha[k]) * c_ahl[a];
                mnx[k] = px - pw * 0.5f; mxx[k] = px + pw * 0.5f;
                mny[k] = py - ph * 0.5f; mxy[k] = py + ph * 0.5f;
                pa[k] = pw * ph;
                ly0 = fminf(ly0, mny[k]);
                ly1 = fmaxf(ly1, mxy[k]);
            }
        }

        // ---- block reduce cell y-extent (fp32) ----
        #pragma unroll
        for (int o = 16; o > 0; o >>= 1) {
            ly0 = fminf(ly0, __shfl_down_sync(0xffffffffu, ly0, o));
            ly1 = fmaxf(ly1, __shfl_down_sync(0xffffffffu, ly1, o));
        }
        if (lane == 0) { s_red_mn[wid] = ly0; s_red_mx[wid] = ly1; }
        __syncthreads();
        if (tid == 0) {
            float m0v = 1e30f, m1v = -1e30f;
            #pragma unroll
            for (int q = 0; q < 8; q++) {
                m0v = fminf(m0v, s_red_mn[q]);
                m1v = fmaxf(m1v, s_red_mx[q]);
            }
            s_ymin = m0v; s_ymax = m1v;
        }
        __syncthreads();

        // ---- warp 0 compacts targets whose y-range can touch the block (margin 1.0 >> fp16 ulp) ----
        if (wid == 0) {
            bool keep = false;
            if (lane < NT) {
                float2 ty2 = s_tyf[lane];
                keep = (ty2.y >= s_ymin - 1.f) && (ty2.x <= s_ymax + 1.f);
            }
            unsigned km = __ballot_sync(0xffffffffu, keep);
            if (keep) {
                int idx = __popc(km & ((1u << lane) - 1u));
                s_ctb[idx]  = s_tb[lane];
                s_cnt2[idx] = s_nt2[lane];
            }
            if (lane == 0) s_live = __popc(km);
        }
        __syncthreads();

        if (active) {
            // pack: pair 0 = cells {0,1}, pair 1 = cells {2,3}
            __half2 cmnx[2], cmxx[2], cmny[2], cmxy[2], maxd[2];
            #pragma unroll
            for (int p = 0; p < 2; p++) {
                cmnx[p] = __floats2half2_rn(mnx[2*p], mnx[2*p+1]);
                cmxx[p] = __floats2half2_rn(mxx[2*p], mxx[2*p+1]);
                cmny[p] = __floats2half2_rn(mny[2*p], mny[2*p+1]);
                cmxy[p] = __floats2half2_rn(mxy[2*p], mxy[2*p+1]);
                maxd[p] = __floats2half2_rn(-60000.f, -60000.f);
            }
            const __half2 zero2  = __floats2half2_rn(0.f, 0.f);
            const __half2 three2 = __floats2half2_rn(3.f, 3.f);

            const int live = s_live;
            for (int t = 0; t < live; t++) {
                TBox tb = s_ctb[t];                     // LDS.128
                __half2 nt2 = s_cnt2[t];                // LDS.32
                #pragma unroll
                for (int p = 0; p < 2; p++) {
                    __half2 iw2h = __hmax2(__hsub2(__hmin2(tb.mxx, cmxx[p]),
                                                   __hmax2(tb.mnx, cmnx[p])), zero2);
                    __half2 ih2h = __hsub2(__hmin2(tb.mxy, cmxy[p]),
                                           __hmax2(tb.mny, cmny[p]));
                    __half2 diff = __hfma2(__hmul2(iw2h, ih2h), three2, nt2);
                    maxd[p] = __hmax2(maxd[p], diff);
                }
            }

            // branch-free epilogue, decision in fp16 domain (same as __hgt against rn(pa))
            const float md[4] = {
                __half2float(__low2half(maxd[0])),
                __half2float(__high2half(maxd[0])),
                __half2float(__low2half(maxd[1])),
                __half2float(__high2half(maxd[1]))
            };
            #pragma unroll
            for (int k = 0; k < 4; k++) {
                float m = (md[k] > __half2float(__float2half_rn(pa[k]))) ? 0.f : 1.f;
                cnum  = fmaf(splus(tcv[k]), m, cnum);
                cmask += m;
            }
        }

        #pragma unroll
        for (int o = 16; o > 0; o >>= 1) {
            cnum  += __shfl_down_sync(0xffffffffu, cnum,  o);
            cmask += __shfl_down_sync(0xffffffffu, cmask, o);
        }
        __shared__ float rn[8], rm[8];
        if (lane == 0) { rn[wid] = cnum; rm[wid] = cmask; }
        __syncthreads();
        if (wid == 0) {
            float n = (lane < 8) ? rn[lane] : 0.f;
            float k = (lane < 8) ? rm[lane] : 0.f;
            #pragma unroll
            for (int o = 4; o > 0; o >>= 1) {
                n += __shfl_down_sync(0xffffffffu, n, o);
                k += __shfl_down_sync(0xffffffffu, k, o);
            }
            if (lane == 0) {
                atomicAdd(&g_conf_num, (double)n);
                atomicAdd(&g_mask_sum, (double)k);
            }
        }
        __syncthreads();
    }

    // ======== grid-wide completion: last block assembles the loss ========
    if (tid == 0) {
        __threadfence();
        int d = atomicAdd(&g_done, 1);
        if (d == TOTAL_BLOCKS - 1) {
            double nobj = (g_nobj > 0) ? (double)g_nobj : 1.0;
            double loss = g_loc_sum / nobj * BOX_RATIO
                        + g_cls_sum / (nobj * (double)NC) * CLS_RATIO
                        + g_conf_num / fmax(g_mask_sum, 1.0) * BALANCE_L * OBJ_RATIO;
            out[0] = (float)loss;
            // self-reset for the next graph replay
            g_conf_num = 0.0; g_mask_sum = 0.0; g_loc_sum = 0.0; g_cls_sum = 0.0;
            g_nobj = 0; g_done = 0;
        }
    }
}

// ---------------- launcher ----------------
extern "C" void kernel_launch(void* const* d_in, const int* in_sizes, int n_in,
                              void* d_out, int out_size) {
    const float* input   = (const float*)d_in[0];
    const float* targets = (const float*)d_in[1];
    float* out = (float*)d_out;
    (void)in_sizes; (void)n_in; (void)out_size;

    dim3 grid(NVB + 1, BS);
    k_fused<<<grid, 256>>>(input, targets, out);
}